// round 1
// baseline (speedup 1.0000x reference)
#include <cuda_runtime.h>
#include <math.h>

#define D_MODEL  1024
#define N_HEADS  16
#define HEAD_DIM 64
#define BATCH    2
#define SEQ      2048
#define M_TOTAL  (BATCH * SEQ)   // 4096

// Scratch for Q, K, V projections: [B*S, D_MODEL] each, layout [B,S,H,Hd]
__device__ float g_Q[(size_t)M_TOTAL * D_MODEL];
__device__ float g_K[(size_t)M_TOTAL * D_MODEL];
__device__ float g_V[(size_t)M_TOTAL * D_MODEL];

// ---------------------------------------------------------------------------
// QKV projection: Y[m,n] = sum_k x[m,k] * W[n,k]   (NT GEMM, both row-major)
// Tiles: 128x128x16, 256 threads, 8x8 per thread (2x2 split of 4x4 quads).
// grid = (M/128, N/128, 3)  where z selects {Wq,Wk,Wv} -> {g_Q,g_K,g_V}
// ---------------------------------------------------------------------------
#define GBM 128
#define GBN 128
#define GBK 16

__global__ void __launch_bounds__(256) qkv_gemm_kernel(
    const float* __restrict__ x,
    const float* __restrict__ Wq,
    const float* __restrict__ Wk,
    const float* __restrict__ Wv)
{
    __shared__ float As[GBK][GBM];
    __shared__ float Bs[GBK][GBN];

    const float* W;
    float* Y;
    if (blockIdx.z == 0)      { W = Wq; Y = g_Q; }
    else if (blockIdx.z == 1) { W = Wk; Y = g_K; }
    else                      { W = Wv; Y = g_V; }

    const int tid  = threadIdx.x;
    const int tx   = tid & 15;
    const int ty   = tid >> 4;
    const int row0 = blockIdx.x * GBM;
    const int col0 = blockIdx.y * GBN;

    float acc[8][8];
    #pragma unroll
    for (int i = 0; i < 8; i++)
        #pragma unroll
        for (int j = 0; j < 8; j++) acc[i][j] = 0.f;

    for (int k0 = 0; k0 < D_MODEL; k0 += GBK) {
        // Load 128x16 tiles of x and W (transposed into smem as [k][m]).
        #pragma unroll
        for (int it = 0; it < 2; it++) {
            int idx = tid + it * 256;        // float4 index, 512 total
            int r   = idx >> 2;              // 0..127
            int c4  = (idx & 3) * 4;         // 0,4,8,12
            float4 va = *(const float4*)(x + (size_t)(row0 + r) * D_MODEL + k0 + c4);
            As[c4 + 0][r] = va.x; As[c4 + 1][r] = va.y;
            As[c4 + 2][r] = va.z; As[c4 + 3][r] = va.w;
            float4 vb = *(const float4*)(W + (size_t)(col0 + r) * D_MODEL + k0 + c4);
            Bs[c4 + 0][r] = vb.x; Bs[c4 + 1][r] = vb.y;
            Bs[c4 + 2][r] = vb.z; Bs[c4 + 3][r] = vb.w;
        }
        __syncthreads();

        #pragma unroll
        for (int k = 0; k < GBK; k++) {
            float a[8], b[8];
            *(float4*)&a[0] = *(const float4*)&As[k][ty * 4];
            *(float4*)&a[4] = *(const float4*)&As[k][64 + ty * 4];
            *(float4*)&b[0] = *(const float4*)&Bs[k][tx * 4];
            *(float4*)&b[4] = *(const float4*)&Bs[k][64 + tx * 4];
            #pragma unroll
            for (int i = 0; i < 8; i++)
                #pragma unroll
                for (int j = 0; j < 8; j++)
                    acc[i][j] = fmaf(a[i], b[j], acc[i][j]);
        }
        __syncthreads();
    }

    #pragma unroll
    for (int ih = 0; ih < 2; ih++) {
        #pragma unroll
        for (int i = 0; i < 4; i++) {
            int r = row0 + ih * 64 + ty * 4 + i;
            #pragma unroll
            for (int jh = 0; jh < 2; jh++) {
                int c = col0 + jh * 64 + tx * 4;
                float4 v = make_float4(acc[ih * 4 + i][jh * 4 + 0],
                                       acc[ih * 4 + i][jh * 4 + 1],
                                       acc[ih * 4 + i][jh * 4 + 2],
                                       acc[ih * 4 + i][jh * 4 + 3]);
                *(float4*)(Y + (size_t)r * D_MODEL + c) = v;
            }
        }
    }
}

// ---------------------------------------------------------------------------
// Flash attention (fp32, online softmax).
// grid = (SEQ/64, N_HEADS, BATCH), 256 threads.
// Each block: 64 query rows of one (b,h); iterate kv tiles of 64.
// Thread (ty,tx): owns 4 q-rows (i0=ty*4) and 4 cols (j0=tx*4) of the S/P
// tile and of the output accumulator. Row stats reduced over the 16-lane
// tx-group via shfl_xor (offsets 8,4,2,1 stay within a 16-lane half-warp).
// ---------------------------------------------------------------------------
#define KPAD 68   // K tile row stride (pad to avoid bank conflicts)

__global__ void __launch_bounds__(256) attn_kernel(float* __restrict__ out)
{
    extern __shared__ float sm[];
    float* Qs = sm;                         // 64*64
    float* Ks = Qs + 64 * 64;               // 64*KPAD
    float* Vs = Ks + 64 * KPAD;             // 64*64
    float* Ps = Vs + 64 * 64;               // 64*64

    const int tid = threadIdx.x;
    const int tx  = tid & 15;
    const int ty  = tid >> 4;
    const int qt  = blockIdx.x;
    const int h   = blockIdx.y;
    const int b   = blockIdx.z;

    const size_t head_off = (size_t)h * HEAD_DIM;
    const size_t base_row = (size_t)b * SEQ;

    // Load Q tile (prescaled by 1/sqrt(Hd) = 0.125)
    #pragma unroll
    for (int it = 0; it < 4; it++) {
        int idx = tid + it * 256;            // 1024 float4s
        int r   = idx >> 4;                  // 0..63
        int c4  = (idx & 15) * 4;            // 0..60
        float4 v = *(const float4*)(g_Q + (base_row + qt * 64 + r) * D_MODEL + head_off + c4);
        Qs[r * 64 + c4 + 0] = v.x * 0.125f;
        Qs[r * 64 + c4 + 1] = v.y * 0.125f;
        Qs[r * 64 + c4 + 2] = v.z * 0.125f;
        Qs[r * 64 + c4 + 3] = v.w * 0.125f;
    }

    float m[4], l[4], acc[4][4];
    #pragma unroll
    for (int i = 0; i < 4; i++) {
        m[i] = -INFINITY;
        l[i] = 0.f;
        #pragma unroll
        for (int c = 0; c < 4; c++) acc[i][c] = 0.f;
    }

    const int i0 = ty * 4;
    const int j0 = tx * 4;

    for (int t = 0; t < SEQ / 64; t++) {
        __syncthreads();   // previous Ps/Vs fully consumed
        // Load K, V tiles
        #pragma unroll
        for (int it = 0; it < 4; it++) {
            int idx = tid + it * 256;
            int r   = idx >> 4;
            int c4  = (idx & 15) * 4;
            const size_t grow = (base_row + t * 64 + r) * D_MODEL + head_off + c4;
            float4 kv = *(const float4*)(g_K + grow);
            Ks[r * KPAD + c4 + 0] = kv.x;
            Ks[r * KPAD + c4 + 1] = kv.y;
            Ks[r * KPAD + c4 + 2] = kv.z;
            Ks[r * KPAD + c4 + 3] = kv.w;
            float4 vv = *(const float4*)(g_V + grow);
            *(float4*)&Vs[r * 64 + c4] = vv;
        }
        __syncthreads();

        // Scores: s[i][j] = Qs[i0+i,:] . Ks[j0+j,:]
        float s[4][4];
        #pragma unroll
        for (int i = 0; i < 4; i++)
            #pragma unroll
            for (int j = 0; j < 4; j++) s[i][j] = 0.f;

        #pragma unroll
        for (int d = 0; d < 64; d += 4) {
            float4 a[4], kk[4];
            #pragma unroll
            for (int i = 0; i < 4; i++) a[i]  = *(const float4*)&Qs[(i0 + i) * 64 + d];
            #pragma unroll
            for (int j = 0; j < 4; j++) kk[j] = *(const float4*)&Ks[(j0 + j) * KPAD + d];
            #pragma unroll
            for (int i = 0; i < 4; i++)
                #pragma unroll
                for (int j = 0; j < 4; j++) {
                    s[i][j] = fmaf(a[i].x, kk[j].x, s[i][j]);
                    s[i][j] = fmaf(a[i].y, kk[j].y, s[i][j]);
                    s[i][j] = fmaf(a[i].z, kk[j].z, s[i][j]);
                    s[i][j] = fmaf(a[i].w, kk[j].w, s[i][j]);
                }
        }

        // Online softmax update
        #pragma unroll
        for (int i = 0; i < 4; i++) {
            float tm = fmaxf(fmaxf(s[i][0], s[i][1]), fmaxf(s[i][2], s[i][3]));
            #pragma unroll
            for (int o = 8; o > 0; o >>= 1)
                tm = fmaxf(tm, __shfl_xor_sync(0xffffffffu, tm, o));
            float nm    = fmaxf(m[i], tm);
            float alpha = __expf(m[i] - nm);
            m[i] = nm;
            float p0 = __expf(s[i][0] - nm);
            float p1 = __expf(s[i][1] - nm);
            float p2 = __expf(s[i][2] - nm);
            float p3 = __expf(s[i][3] - nm);
            l[i] = l[i] * alpha + (p0 + p1 + p2 + p3);
            #pragma unroll
            for (int c = 0; c < 4; c++) acc[i][c] *= alpha;
            *(float4*)&Ps[(i0 + i) * 64 + j0] = make_float4(p0, p1, p2, p3);
        }
        __syncthreads();

        // acc[i][c] += sum_j Ps[i0+i][j] * Vs[j][d0+c]  (d0 == j0 == tx*4)
        #pragma unroll
        for (int j = 0; j < 64; j += 4) {
            float4 v0 = *(const float4*)&Vs[(j + 0) * 64 + j0];
            float4 v1 = *(const float4*)&Vs[(j + 1) * 64 + j0];
            float4 v2 = *(const float4*)&Vs[(j + 2) * 64 + j0];
            float4 v3 = *(const float4*)&Vs[(j + 3) * 64 + j0];
            #pragma unroll
            for (int i = 0; i < 4; i++) {
                float4 p = *(const float4*)&Ps[(i0 + i) * 64 + j];
                acc[i][0] = fmaf(p.x, v0.x, acc[i][0]);
                acc[i][1] = fmaf(p.x, v0.y, acc[i][1]);
                acc[i][2] = fmaf(p.x, v0.z, acc[i][2]);
                acc[i][3] = fmaf(p.x, v0.w, acc[i][3]);
                acc[i][0] = fmaf(p.y, v1.x, acc[i][0]);
                acc[i][1] = fmaf(p.y, v1.y, acc[i][1]);
                acc[i][2] = fmaf(p.y, v1.z, acc[i][2]);
                acc[i][3] = fmaf(p.y, v1.w, acc[i][3]);
                acc[i][0] = fmaf(p.z, v2.x, acc[i][0]);
                acc[i][1] = fmaf(p.z, v2.y, acc[i][1]);
                acc[i][2] = fmaf(p.z, v2.z, acc[i][2]);
                acc[i][3] = fmaf(p.z, v2.w, acc[i][3]);
                acc[i][0] = fmaf(p.w, v3.x, acc[i][0]);
                acc[i][1] = fmaf(p.w, v3.y, acc[i][1]);
                acc[i][2] = fmaf(p.w, v3.z, acc[i][2]);
                acc[i][3] = fmaf(p.w, v3.w, acc[i][3]);
            }
        }
    }

    // Reduce row sums across the 16-lane tx-group, normalize, write out.
    #pragma unroll
    for (int i = 0; i < 4; i++) {
        float li = l[i];
        #pragma unroll
        for (int o = 8; o > 0; o >>= 1)
            li += __shfl_xor_sync(0xffffffffu, li, o);
        float inv = 1.f / li;
        float4 v = make_float4(acc[i][0] * inv, acc[i][1] * inv,
                               acc[i][2] * inv, acc[i][3] * inv);
        *(float4*)(out + (base_row + qt * 64 + i0 + i) * D_MODEL + head_off + j0) = v;
    }
}

// ---------------------------------------------------------------------------
extern "C" void kernel_launch(void* const* d_in, const int* in_sizes, int n_in,
                              void* d_out, int out_size)
{
    (void)in_sizes; (void)n_in; (void)out_size;
    const float* x  = (const float*)d_in[0];
    const float* Wq = (const float*)d_in[1];
    const float* Wk = (const float*)d_in[2];
    const float* Wv = (const float*)d_in[3];
    float* out = (float*)d_out;

    dim3 ggrid(M_TOTAL / GBM, D_MODEL / GBN, 3);   // (32, 8, 3)
    qkv_gemm_kernel<<<ggrid, 256>>>(x, Wq, Wk, Wv);

    const int smem_bytes = (64 * 64 + 64 * KPAD + 64 * 64 + 64 * 64) * (int)sizeof(float);
    cudaFuncSetAttribute(attn_kernel, cudaFuncAttributeMaxDynamicSharedMemorySize, smem_bytes);
    dim3 agrid(SEQ / 64, N_HEADS, BATCH);          // (32, 16, 2)
    attn_kernel<<<agrid, 256, smem_bytes>>>(out);
}

// round 3
// speedup vs baseline: 3.1217x; 3.1217x over previous
#include <cuda_runtime.h>
#include <cuda_bf16.h>
#include <math.h>
#include <stdint.h>

#define D_MODEL  1024
#define N_HEADS  16
#define HEAD_DIM 64
#define BATCH    2
#define SEQ      2048
#define M_TOTAL  (BATCH * SEQ)   // 4096

#define QSCALE 0.180336884f      // 0.125 * log2(e)

// ---------------------------------------------------------------------------
// Device scratch (hi/lo bf16 splits). Total ~76 MB.
// ---------------------------------------------------------------------------
__device__ __nv_bfloat16 g_xh[(size_t)M_TOTAL * D_MODEL];
__device__ __nv_bfloat16 g_xl[(size_t)M_TOTAL * D_MODEL];
__device__ __nv_bfloat16 g_Wh[3][(size_t)D_MODEL * D_MODEL];
__device__ __nv_bfloat16 g_Wl[3][(size_t)D_MODEL * D_MODEL];
__device__ __nv_bfloat16 g_Qh[(size_t)M_TOTAL * D_MODEL];
__device__ __nv_bfloat16 g_Ql[(size_t)M_TOTAL * D_MODEL];
__device__ __nv_bfloat16 g_Kh[(size_t)M_TOTAL * D_MODEL];
__device__ __nv_bfloat16 g_Kl[(size_t)M_TOTAL * D_MODEL];
__device__ __nv_bfloat16 g_Vh[(size_t)M_TOTAL * D_MODEL];
__device__ __nv_bfloat16 g_Vl[(size_t)M_TOTAL * D_MODEL];

// ---------------------------------------------------------------------------
// Helpers
// ---------------------------------------------------------------------------
__device__ __forceinline__ uint32_t smem_u32(const void* p) {
    uint32_t a;
    asm("{ .reg .u64 t; cvta.to.shared.u64 t, %1; cvt.u32.u64 %0, t; }"
        : "=r"(a) : "l"(p));
    return a;
}
__device__ __forceinline__ uint32_t sw128(uint32_t off) {
    return off ^ ((off >> 3) & 0x70);
}
__device__ __forceinline__ float ex2f(float x) {
    float y;
    asm("ex2.approx.ftz.f32 %0, %1;" : "=f"(y) : "f"(x));
    return y;
}
// bf16 mma: D(f32) += A(bf16) * B(bf16),  m16n8k16, A row-major, B col-major
__device__ __forceinline__ void mma_bf16(float* c, const uint32_t* a, const uint32_t* b) {
    asm volatile(
        "mma.sync.aligned.m16n8k16.row.col.f32.bf16.bf16.f32 "
        "{%0,%1,%2,%3}, {%4,%5,%6,%7}, {%8,%9}, {%0,%1,%2,%3};"
        : "+f"(c[0]), "+f"(c[1]), "+f"(c[2]), "+f"(c[3])
        : "r"(a[0]), "r"(a[1]), "r"(a[2]), "r"(a[3]), "r"(b[0]), "r"(b[1]));
}
__device__ __forceinline__ void ldsm4(uint32_t* r, uint32_t addr) {
    asm volatile("ldmatrix.sync.aligned.m8n8.x4.shared.b16 {%0,%1,%2,%3}, [%4];"
        : "=r"(r[0]), "=r"(r[1]), "=r"(r[2]), "=r"(r[3]) : "r"(addr));
}
__device__ __forceinline__ void ldsm4t(uint32_t* r, uint32_t addr) {
    asm volatile("ldmatrix.sync.aligned.m8n8.x4.trans.shared.b16 {%0,%1,%2,%3}, [%4];"
        : "=r"(r[0]), "=r"(r[1]), "=r"(r[2]), "=r"(r[3]) : "r"(addr));
}
// split (a,b) into packed-hi bf16x2 (return) and packed-lo bf16x2 (lo_out)
__device__ __forceinline__ uint32_t split_pair(float a, float b, uint32_t& lo_out) {
    __nv_bfloat16 ha = __float2bfloat16_rn(a);
    __nv_bfloat16 hb = __float2bfloat16_rn(b);
    __nv_bfloat16 la = __float2bfloat16_rn(a - __bfloat162float(ha));
    __nv_bfloat16 lb = __float2bfloat16_rn(b - __bfloat162float(hb));
    lo_out = (uint32_t)__bfloat16_as_ushort(la) | ((uint32_t)__bfloat16_as_ushort(lb) << 16);
    return (uint32_t)__bfloat16_as_ushort(ha) | ((uint32_t)__bfloat16_as_ushort(hb) << 16);
}

// ---------------------------------------------------------------------------
// Split fp32 tensor into hi/lo bf16
// ---------------------------------------------------------------------------
__global__ void __launch_bounds__(256) split_kernel(
    const float* __restrict__ src, __nv_bfloat16* __restrict__ hi,
    __nv_bfloat16* __restrict__ lo, int n4)
{
    int i = blockIdx.x * 256 + threadIdx.x;
    if (i < n4) {
        float4 v = ((const float4*)src)[i];
        uint32_t l0, l1;
        uint32_t h0 = split_pair(v.x, v.y, l0);
        uint32_t h1 = split_pair(v.z, v.w, l1);
        ((uint2*)hi)[i] = make_uint2(h0, h1);
        ((uint2*)lo)[i] = make_uint2(l0, l1);
    }
}

// ---------------------------------------------------------------------------
// QKV GEMM via mma.sync:  Y[m,n] = sum_k x[m,k] * W[n,k]  (bf16x3 split)
// CTA 128x128, k-chunks of 64; 8 warps, warp tile m32 x n64.
// Epilogue: Y -> hi/lo bf16 (Q pre-scaled by QSCALE).
// smem: Ah 0, Al 16K, Bh 32K, Bl 48K  (each [128 rows][64 bf16], SW128)
// ---------------------------------------------------------------------------
__global__ void __launch_bounds__(256) qkv_mma(void)
{
    extern __shared__ char sm[];
    const uint32_t sb = smem_u32(sm);
    const int tid = threadIdx.x, wid = tid >> 5, lane = tid & 31;
    const int mb = blockIdx.x, nb = blockIdx.y, z = blockIdx.z;

    const __nv_bfloat16* Bh_g = g_Wh[z];
    const __nv_bfloat16* Bl_g = g_Wl[z];
    __nv_bfloat16 *Dh, *Dl;
    if (z == 0)      { Dh = g_Qh; Dl = g_Ql; }
    else if (z == 1) { Dh = g_Kh; Dl = g_Kl; }
    else             { Dh = g_Vh; Dl = g_Vl; }
    const float scale = (z == 0) ? QSCALE : 1.0f;

    const int wm = (wid & 3) * 32;     // warp m offset within 128
    const int wn = (wid >> 2) * 64;    // warp n offset within 128

    float acc[2][8][4];
    #pragma unroll
    for (int mi = 0; mi < 2; mi++)
        #pragma unroll
        for (int nf = 0; nf < 8; nf++)
            #pragma unroll
            for (int r = 0; r < 4; r++) acc[mi][nf][r] = 0.f;

    for (int k0 = 0; k0 < D_MODEL; k0 += 64) {
        __syncthreads();
        #pragma unroll
        for (int it = 0; it < 4; it++) {
            int idx = tid + it * 256;          // 1024 chunk-slots
            int r = idx >> 3, c = idx & 7;
            size_t ga = (size_t)(mb * 128 + r) * D_MODEL + k0 + c * 8;
            size_t gb = (size_t)(nb * 128 + r) * D_MODEL + k0 + c * 8;
            uint32_t so = sw128((uint32_t)(r * 128 + c * 16));
            *(uint4*)(sm +     0 + so) = *(const uint4*)(g_xh + ga);
            *(uint4*)(sm + 16384 + so) = *(const uint4*)(g_xl + ga);
            *(uint4*)(sm + 32768 + so) = *(const uint4*)(Bh_g + gb);
            *(uint4*)(sm + 49152 + so) = *(const uint4*)(Bl_g + gb);
        }
        __syncthreads();

        #pragma unroll
        for (int ks = 0; ks < 4; ks++) {
            uint32_t ah[2][4], al[2][4];
            #pragma unroll
            for (int mi = 0; mi < 2; mi++) {
                uint32_t row  = wm + mi * 16 + (lane & 15);
                uint32_t byte = ks * 32 + (lane >> 4) * 16;
                uint32_t so   = sw128(row * 128 + byte);
                ldsm4(ah[mi], sb +     0 + so);
                ldsm4(al[mi], sb + 16384 + so);
            }
            #pragma unroll
            for (int ni = 0; ni < 4; ni++) {
                uint32_t bh[4], bl[4];
                uint32_t t    = lane >> 3;
                uint32_t row  = wn + ni * 16 + (lane & 7) + 8 * (t >> 1);
                uint32_t byte = ks * 32 + 16 * (t & 1);
                uint32_t so   = sw128(row * 128 + byte);
                ldsm4(bh, sb + 32768 + so);
                ldsm4(bl, sb + 49152 + so);
                #pragma unroll
                for (int sub = 0; sub < 2; sub++) {
                    #pragma unroll
                    for (int mi = 0; mi < 2; mi++) {
                        mma_bf16(acc[mi][ni * 2 + sub], ah[mi], bh + sub * 2);
                        mma_bf16(acc[mi][ni * 2 + sub], ah[mi], bl + sub * 2);
                        mma_bf16(acc[mi][ni * 2 + sub], al[mi], bh + sub * 2);
                    }
                }
            }
        }
    }

    // Epilogue: split to hi/lo bf16 pairs
    const int g  = lane >> 2;
    const int c2 = (lane & 3) * 2;
    #pragma unroll
    for (int mi = 0; mi < 2; mi++) {
        const size_t r0 = (size_t)(mb * 128 + wm + mi * 16 + g);
        #pragma unroll
        for (int nf = 0; nf < 8; nf++) {
            const int col = nb * 128 + wn + nf * 8 + c2;
            uint32_t lo0, lo1;
            uint32_t hi0 = split_pair(acc[mi][nf][0] * scale, acc[mi][nf][1] * scale, lo0);
            uint32_t hi1 = split_pair(acc[mi][nf][2] * scale, acc[mi][nf][3] * scale, lo1);
            *(uint32_t*)(Dh +  r0      * D_MODEL + col) = hi0;
            *(uint32_t*)(Dl +  r0      * D_MODEL + col) = lo0;
            *(uint32_t*)(Dh + (r0 + 8) * D_MODEL + col) = hi1;
            *(uint32_t*)(Dl + (r0 + 8) * D_MODEL + col) = lo1;
        }
    }
}

// ---------------------------------------------------------------------------
// Flash attention via mma.sync.  grid (SEQ/128, H, B), 256 threads, 8 warps.
// Warp w owns q-rows [w*16, w*16+16); kv tiles of 64.
// smem: Qh 0, Ql 16K, Kh 32K, Kl 40K, Vh 48K, Vl 56K (rows 128B, SW128)
// ---------------------------------------------------------------------------
__global__ void __launch_bounds__(256) attn_mma(float* __restrict__ out)
{
    extern __shared__ char sm[];
    const uint32_t sb = smem_u32(sm);
    const int tid = threadIdx.x, wid = tid >> 5, lane = tid & 31;
    const int qb = blockIdx.x, h = blockIdx.y, b = blockIdx.z;
    const size_t hoff = (size_t)h * HEAD_DIM;
    const size_t brow = (size_t)b * SEQ;

    // Load Q tile [128 x 64] hi/lo
    #pragma unroll
    for (int it = 0; it < 4; it++) {
        int idx = tid + it * 256;
        int r = idx >> 3, c = idx & 7;
        size_t ga = (brow + qb * 128 + r) * D_MODEL + hoff + c * 8;
        uint32_t so = sw128((uint32_t)(r * 128 + c * 16));
        *(uint4*)(sm +     0 + so) = *(const uint4*)(g_Qh + ga);
        *(uint4*)(sm + 16384 + so) = *(const uint4*)(g_Ql + ga);
    }
    __syncthreads();

    // Q fragments held in registers across the kv loop
    uint32_t qh[4][4], ql[4][4];
    #pragma unroll
    for (int kc = 0; kc < 4; kc++) {
        uint32_t row  = wid * 16 + (lane & 15);
        uint32_t byte = kc * 32 + (lane >> 4) * 16;
        uint32_t so   = sw128(row * 128 + byte);
        ldsm4(qh[kc], sb +     0 + so);
        ldsm4(ql[kc], sb + 16384 + so);
    }

    float accO[8][4];
    #pragma unroll
    for (int f = 0; f < 8; f++)
        #pragma unroll
        for (int r = 0; r < 4; r++) accO[f][r] = 0.f;
    float mrow0 = -INFINITY, mrow1 = -INFINITY;
    float lrow0 = 0.f, lrow1 = 0.f;

    for (int t = 0; t < SEQ / 64; t++) {
        __syncthreads();
        #pragma unroll
        for (int it = 0; it < 2; it++) {
            int idx = tid + it * 256;          // 512 chunk-slots
            int r = idx >> 3, c = idx & 7;
            size_t ga = (brow + t * 64 + r) * D_MODEL + hoff + c * 8;
            uint32_t so = sw128((uint32_t)(r * 128 + c * 16));
            *(uint4*)(sm + 32768 + so) = *(const uint4*)(g_Kh + ga);
            *(uint4*)(sm + 40960 + so) = *(const uint4*)(g_Kl + ga);
            *(uint4*)(sm + 49152 + so) = *(const uint4*)(g_Vh + ga);
            *(uint4*)(sm + 57344 + so) = *(const uint4*)(g_Vl + ga);
        }
        __syncthreads();

        // S = Q K^T (scaled, log2 domain)
        float accS[8][4];
        #pragma unroll
        for (int f = 0; f < 8; f++)
            #pragma unroll
            for (int r = 0; r < 4; r++) accS[f][r] = 0.f;

        #pragma unroll
        for (int kc = 0; kc < 4; kc++) {
            #pragma unroll
            for (int ni = 0; ni < 4; ni++) {
                uint32_t bh[4], bl[4];
                uint32_t tt   = lane >> 3;
                uint32_t row  = ni * 16 + (lane & 7) + 8 * (tt >> 1);
                uint32_t byte = kc * 32 + 16 * (tt & 1);
                uint32_t so   = sw128(row * 128 + byte);
                ldsm4(bh, sb + 32768 + so);
                ldsm4(bl, sb + 40960 + so);
                #pragma unroll
                for (int sub = 0; sub < 2; sub++) {
                    mma_bf16(accS[ni * 2 + sub], qh[kc], bh + sub * 2);
                    mma_bf16(accS[ni * 2 + sub], qh[kc], bl + sub * 2);
                    mma_bf16(accS[ni * 2 + sub], ql[kc], bh + sub * 2);
                }
            }
        }

        // Online softmax (rows r0 = ..+g, r1 = ..+g+8), log2 domain
        float mx0 = -INFINITY, mx1 = -INFINITY;
        #pragma unroll
        for (int f = 0; f < 8; f++) {
            mx0 = fmaxf(mx0, fmaxf(accS[f][0], accS[f][1]));
            mx1 = fmaxf(mx1, fmaxf(accS[f][2], accS[f][3]));
        }
        mx0 = fmaxf(mx0, __shfl_xor_sync(0xffffffffu, mx0, 1));
        mx0 = fmaxf(mx0, __shfl_xor_sync(0xffffffffu, mx0, 2));
        mx1 = fmaxf(mx1, __shfl_xor_sync(0xffffffffu, mx1, 1));
        mx1 = fmaxf(mx1, __shfl_xor_sync(0xffffffffu, mx1, 2));
        float nm0 = fmaxf(mrow0, mx0);
        float nm1 = fmaxf(mrow1, mx1);
        float a0 = ex2f(mrow0 - nm0);
        float a1 = ex2f(mrow1 - nm1);
        mrow0 = nm0; mrow1 = nm1;

        float s0 = 0.f, s1 = 0.f;
        #pragma unroll
        for (int f = 0; f < 8; f++) {
            accS[f][0] = ex2f(accS[f][0] - nm0);
            accS[f][1] = ex2f(accS[f][1] - nm0);
            accS[f][2] = ex2f(accS[f][2] - nm1);
            accS[f][3] = ex2f(accS[f][3] - nm1);
            s0 += accS[f][0] + accS[f][1];
            s1 += accS[f][2] + accS[f][3];
        }
        s0 += __shfl_xor_sync(0xffffffffu, s0, 1);
        s0 += __shfl_xor_sync(0xffffffffu, s0, 2);
        s1 += __shfl_xor_sync(0xffffffffu, s1, 1);
        s1 += __shfl_xor_sync(0xffffffffu, s1, 2);
        lrow0 = lrow0 * a0 + s0;
        lrow1 = lrow1 * a1 + s1;
        #pragma unroll
        for (int f = 0; f < 8; f++) {
            accO[f][0] *= a0; accO[f][1] *= a0;
            accO[f][2] *= a1; accO[f][3] *= a1;
        }

        // O += P V   (P from accS registers, split hi/lo in place)
        #pragma unroll
        for (int kc = 0; kc < 4; kc++) {
            const int f0 = 2 * kc, f1 = 2 * kc + 1;
            uint32_t pah[4], pal[4];
            pah[0] = split_pair(accS[f0][0], accS[f0][1], pal[0]);
            pah[1] = split_pair(accS[f0][2], accS[f0][3], pal[1]);
            pah[2] = split_pair(accS[f1][0], accS[f1][1], pal[2]);
            pah[3] = split_pair(accS[f1][2], accS[f1][3], pal[3]);
            #pragma unroll
            for (int ni = 0; ni < 4; ni++) {
                uint32_t vh[4], vl[4];
                uint32_t row  = kc * 16 + (lane & 7) + 8 * ((lane >> 3) & 1);
                uint32_t byte = ni * 32 + (lane >> 4) * 16;
                uint32_t so   = sw128(row * 128 + byte);
                ldsm4t(vh, sb + 49152 + so);
                ldsm4t(vl, sb + 57344 + so);
                #pragma unroll
                for (int sub = 0; sub < 2; sub++) {
                    mma_bf16(accO[ni * 2 + sub], pah, vh + sub * 2);
                    mma_bf16(accO[ni * 2 + sub], pah, vl + sub * 2);
                    mma_bf16(accO[ni * 2 + sub], pal, vh + sub * 2);
                }
            }
        }
    }

    // Normalize + store
    const float inv0 = 1.f / lrow0;
    const float inv1 = 1.f / lrow1;
    const int g  = lane >> 2;
    const int c2 = (lane & 3) * 2;
    const size_t r0 = brow + qb * 128 + wid * 16 + g;
    #pragma unroll
    for (int f = 0; f < 8; f++) {
        const size_t d = hoff + f * 8 + c2;
        float2 v0 = make_float2(accO[f][0] * inv0, accO[f][1] * inv0);
        float2 v1 = make_float2(accO[f][2] * inv1, accO[f][3] * inv1);
        *(float2*)(out +  r0      * D_MODEL + d) = v0;
        *(float2*)(out + (r0 + 8) * D_MODEL + d) = v1;
    }
}

// ---------------------------------------------------------------------------
extern "C" void kernel_launch(void* const* d_in, const int* in_sizes, int n_in,
                              void* d_out, int out_size)
{
    (void)in_sizes; (void)n_in; (void)out_size;
    const float* x  = (const float*)d_in[0];
    const float* Wq = (const float*)d_in[1];
    const float* Wk = (const float*)d_in[2];
    const float* Wv = (const float*)d_in[3];
    float* out = (float*)d_out;

    // resolve device-scratch addresses
    __nv_bfloat16 *xh, *xl, *wh0, *wl0, *wh1, *wl1, *wh2, *wl2;
    cudaGetSymbolAddress((void**)&xh,  g_xh);
    cudaGetSymbolAddress((void**)&xl,  g_xl);
    cudaGetSymbolAddress((void**)&wh0, g_Wh);
    cudaGetSymbolAddress((void**)&wl0, g_Wl);
    wh1 = wh0 + (size_t)D_MODEL * D_MODEL; wh2 = wh1 + (size_t)D_MODEL * D_MODEL;
    wl1 = wl0 + (size_t)D_MODEL * D_MODEL; wl2 = wl1 + (size_t)D_MODEL * D_MODEL;

    const int nx4 = M_TOTAL * D_MODEL / 4;       // 1,048,576
    const int nw4 = D_MODEL * D_MODEL / 4;       // 262,144
    split_kernel<<<(nx4 + 255) / 256, 256>>>(x,  xh,  xl,  nx4);
    split_kernel<<<(nw4 + 255) / 256, 256>>>(Wq, wh0, wl0, nw4);
    split_kernel<<<(nw4 + 255) / 256, 256>>>(Wk, wh1, wl1, nw4);
    split_kernel<<<(nw4 + 255) / 256, 256>>>(Wv, wh2, wl2, nw4);

    cudaFuncSetAttribute(qkv_mma, cudaFuncAttributeMaxDynamicSharedMemorySize, 65536);
    dim3 ggrid(M_TOTAL / 128, D_MODEL / 128, 3);   // (32, 8, 3)
    qkv_mma<<<ggrid, 256, 65536>>>();

    cudaFuncSetAttribute(attn_mma, cudaFuncAttributeMaxDynamicSharedMemorySize, 65536);
    dim3 agrid(SEQ / 128, N_HEADS, BATCH);         // (16, 16, 2)
    attn_mma<<<agrid, 256, 65536>>>(out);
}

// round 4
// speedup vs baseline: 4.0489x; 1.2970x over previous
#include <cuda_runtime.h>
#include <cuda_bf16.h>
#include <math.h>
#include <stdint.h>

#define D_MODEL  1024
#define N_HEADS  16
#define HEAD_DIM 64
#define BATCH    2
#define SEQ      2048
#define M_TOTAL  (BATCH * SEQ)   // 4096

#define QSCALE 0.180336884f      // 0.125 * log2(e)

// ---------------------------------------------------------------------------
// Device scratch (hi/lo bf16 splits)
// ---------------------------------------------------------------------------
__device__ __nv_bfloat16 g_xh[(size_t)M_TOTAL * D_MODEL];
__device__ __nv_bfloat16 g_xl[(size_t)M_TOTAL * D_MODEL];
__device__ __nv_bfloat16 g_Wh[3][(size_t)D_MODEL * D_MODEL];
__device__ __nv_bfloat16 g_Wl[3][(size_t)D_MODEL * D_MODEL];
__device__ __nv_bfloat16 g_Qh[(size_t)M_TOTAL * D_MODEL];
__device__ __nv_bfloat16 g_Ql[(size_t)M_TOTAL * D_MODEL];
__device__ __nv_bfloat16 g_Kh[(size_t)M_TOTAL * D_MODEL];
__device__ __nv_bfloat16 g_Kl[(size_t)M_TOTAL * D_MODEL];
__device__ __nv_bfloat16 g_Vh[(size_t)M_TOTAL * D_MODEL];
__device__ __nv_bfloat16 g_Vl[(size_t)M_TOTAL * D_MODEL];

// ---------------------------------------------------------------------------
// Helpers
// ---------------------------------------------------------------------------
__device__ __forceinline__ uint32_t smem_u32(const void* p) {
    uint32_t a;
    asm("{ .reg .u64 t; cvta.to.shared.u64 t, %1; cvt.u32.u64 %0, t; }"
        : "=r"(a) : "l"(p));
    return a;
}
__device__ __forceinline__ uint32_t sw128(uint32_t off) {
    return off ^ ((off >> 3) & 0x70);
}
__device__ __forceinline__ float ex2f(float x) {
    float y;
    asm("ex2.approx.ftz.f32 %0, %1;" : "=f"(y) : "f"(x));
    return y;
}
__device__ __forceinline__ void mma_bf16(float* c, const uint32_t* a, const uint32_t* b) {
    asm volatile(
        "mma.sync.aligned.m16n8k16.row.col.f32.bf16.bf16.f32 "
        "{%0,%1,%2,%3}, {%4,%5,%6,%7}, {%8,%9}, {%0,%1,%2,%3};"
        : "+f"(c[0]), "+f"(c[1]), "+f"(c[2]), "+f"(c[3])
        : "r"(a[0]), "r"(a[1]), "r"(a[2]), "r"(a[3]), "r"(b[0]), "r"(b[1]));
}
__device__ __forceinline__ void ldsm4(uint32_t* r, uint32_t addr) {
    asm volatile("ldmatrix.sync.aligned.m8n8.x4.shared.b16 {%0,%1,%2,%3}, [%4];"
        : "=r"(r[0]), "=r"(r[1]), "=r"(r[2]), "=r"(r[3]) : "r"(addr));
}
__device__ __forceinline__ void ldsm4t(uint32_t* r, uint32_t addr) {
    asm volatile("ldmatrix.sync.aligned.m8n8.x4.trans.shared.b16 {%0,%1,%2,%3}, [%4];"
        : "=r"(r[0]), "=r"(r[1]), "=r"(r[2]), "=r"(r[3]) : "r"(addr));
}
__device__ __forceinline__ void cpa16(uint32_t dst, const void* src) {
    asm volatile("cp.async.ca.shared.global [%0], [%1], 16;"
                 :: "r"(dst), "l"(src));
}
#define CPA_COMMIT() asm volatile("cp.async.commit_group;" ::: "memory")
#define CPA_WAIT0()  asm volatile("cp.async.wait_group 0;"  ::: "memory")

__device__ __forceinline__ uint32_t split_pair(float a, float b, uint32_t& lo_out) {
    __nv_bfloat16 ha = __float2bfloat16_rn(a);
    __nv_bfloat16 hb = __float2bfloat16_rn(b);
    __nv_bfloat16 la = __float2bfloat16_rn(a - __bfloat162float(ha));
    __nv_bfloat16 lb = __float2bfloat16_rn(b - __bfloat162float(hb));
    lo_out = (uint32_t)__bfloat16_as_ushort(la) | ((uint32_t)__bfloat16_as_ushort(lb) << 16);
    return (uint32_t)__bfloat16_as_ushort(ha) | ((uint32_t)__bfloat16_as_ushort(hb) << 16);
}

// ---------------------------------------------------------------------------
// Split fp32 tensor into hi/lo bf16
// ---------------------------------------------------------------------------
__global__ void __launch_bounds__(256) split_kernel(
    const float* __restrict__ src, __nv_bfloat16* __restrict__ hi,
    __nv_bfloat16* __restrict__ lo, int n4)
{
    int i = blockIdx.x * 256 + threadIdx.x;
    if (i < n4) {
        float4 v = ((const float4*)src)[i];
        uint32_t l0, l1;
        uint32_t h0 = split_pair(v.x, v.y, l0);
        uint32_t h1 = split_pair(v.z, v.w, l1);
        ((uint2*)hi)[i] = make_uint2(h0, h1);
        ((uint2*)lo)[i] = make_uint2(l0, l1);
    }
}

// ---------------------------------------------------------------------------
// QKV GEMM (bf16x3), cp.async double-buffered.
// CTA 128x128, k-chunks of 64; 8 warps, warp tile m32 x n64.
// smem per stage (64KB): Ah@0 Al@16K Bh@32K Bl@48K; 2 stages = 128KB.
// ---------------------------------------------------------------------------
#define QKV_STAGE 65536

__global__ void __launch_bounds__(256) qkv_mma(void)
{
    extern __shared__ char sm[];
    const uint32_t sb = smem_u32(sm);
    const int tid = threadIdx.x, wid = tid >> 5, lane = tid & 31;
    const int mb = blockIdx.x, nb = blockIdx.y, z = blockIdx.z;

    const __nv_bfloat16* Bh_g = g_Wh[z];
    const __nv_bfloat16* Bl_g = g_Wl[z];
    __nv_bfloat16 *Dh, *Dl;
    if (z == 0)      { Dh = g_Qh; Dl = g_Ql; }
    else if (z == 1) { Dh = g_Kh; Dl = g_Kl; }
    else             { Dh = g_Vh; Dl = g_Vl; }
    const float scale = (z == 0) ? QSCALE : 1.0f;

    const int wm = (wid & 3) * 32;
    const int wn = (wid >> 2) * 64;

    float acc[2][8][4];
    #pragma unroll
    for (int mi = 0; mi < 2; mi++)
        #pragma unroll
        for (int nf = 0; nf < 8; nf++)
            #pragma unroll
            for (int r = 0; r < 4; r++) acc[mi][nf][r] = 0.f;

    auto load_stage = [&](int ch, int s) {
        const uint32_t sbase = sb + (uint32_t)s * QKV_STAGE;
        #pragma unroll
        for (int it = 0; it < 4; it++) {
            int idx = tid + it * 256;
            int r = idx >> 3, c = idx & 7;
            size_t ga = (size_t)(mb * 128 + r) * D_MODEL + ch * 64 + c * 8;
            size_t gb = (size_t)(nb * 128 + r) * D_MODEL + ch * 64 + c * 8;
            uint32_t so = sw128((uint32_t)(r * 128 + c * 16));
            cpa16(sbase +         so, g_xh + ga);
            cpa16(sbase + 16384 + so, g_xl + ga);
            cpa16(sbase + 32768 + so, Bh_g + gb);
            cpa16(sbase + 49152 + so, Bl_g + gb);
        }
    };

    load_stage(0, 0);
    CPA_COMMIT();

    for (int ch = 0; ch < D_MODEL / 64; ch++) {
        CPA_WAIT0();
        __syncthreads();
        if (ch + 1 < D_MODEL / 64) {
            load_stage(ch + 1, (ch + 1) & 1);
            CPA_COMMIT();
        }
        const uint32_t sbase = sb + (uint32_t)(ch & 1) * QKV_STAGE;

        #pragma unroll
        for (int ks = 0; ks < 4; ks++) {
            uint32_t ah[2][4], al[2][4];
            #pragma unroll
            for (int mi = 0; mi < 2; mi++) {
                uint32_t row  = wm + mi * 16 + (lane & 15);
                uint32_t byte = ks * 32 + (lane >> 4) * 16;
                uint32_t so   = sw128(row * 128 + byte);
                ldsm4(ah[mi], sbase +         so);
                ldsm4(al[mi], sbase + 16384 + so);
            }
            #pragma unroll
            for (int ni = 0; ni < 4; ni++) {
                uint32_t bh[4], bl[4];
                uint32_t t    = lane >> 3;
                uint32_t row  = wn + ni * 16 + (lane & 7) + 8 * (t >> 1);
                uint32_t byte = ks * 32 + 16 * (t & 1);
                uint32_t so   = sw128(row * 128 + byte);
                ldsm4(bh, sbase + 32768 + so);
                ldsm4(bl, sbase + 49152 + so);
                #pragma unroll
                for (int sub = 0; sub < 2; sub++) {
                    #pragma unroll
                    for (int mi = 0; mi < 2; mi++) {
                        mma_bf16(acc[mi][ni * 2 + sub], ah[mi], bh + sub * 2);
                        mma_bf16(acc[mi][ni * 2 + sub], ah[mi], bl + sub * 2);
                        mma_bf16(acc[mi][ni * 2 + sub], al[mi], bh + sub * 2);
                    }
                }
            }
        }
    }

    // Epilogue: split to hi/lo bf16
    const int g  = lane >> 2;
    const int c2 = (lane & 3) * 2;
    #pragma unroll
    for (int mi = 0; mi < 2; mi++) {
        const size_t r0 = (size_t)(mb * 128 + wm + mi * 16 + g);
        #pragma unroll
        for (int nf = 0; nf < 8; nf++) {
            const int col = nb * 128 + wn + nf * 8 + c2;
            uint32_t lo0, lo1;
            uint32_t hi0 = split_pair(acc[mi][nf][0] * scale, acc[mi][nf][1] * scale, lo0);
            uint32_t hi1 = split_pair(acc[mi][nf][2] * scale, acc[mi][nf][3] * scale, lo1);
            *(uint32_t*)(Dh +  r0      * D_MODEL + col) = hi0;
            *(uint32_t*)(Dl +  r0      * D_MODEL + col) = lo0;
            *(uint32_t*)(Dh + (r0 + 8) * D_MODEL + col) = hi1;
            *(uint32_t*)(Dl + (r0 + 8) * D_MODEL + col) = lo1;
        }
    }
}

// ---------------------------------------------------------------------------
// Flash attention (bf16x3 mma), cp.async double-buffered KV.
// grid (SEQ/128, H, B), 128 threads / 4 warps; warp = 32 q-rows (mi=2).
// smem: Qh@0 (16K), Ql@16K; KV stages @32K (+s*32K): Kh+0 Kl+8K Vh+16K Vl+24K.
// ---------------------------------------------------------------------------
#define ATT_KV   32768
#define ATT_SMEM (32768 + 2 * 32768)   // 96KB

__global__ void __launch_bounds__(128) attn_mma(float* __restrict__ out)
{
    extern __shared__ char sm[];
    const uint32_t sb = smem_u32(sm);
    const int tid = threadIdx.x, wid = tid >> 5, lane = tid & 31;
    const int qb = blockIdx.x, h = blockIdx.y, b = blockIdx.z;
    const size_t hoff = (size_t)h * HEAD_DIM;
    const size_t brow = (size_t)b * SEQ;
    const int wm = wid * 32;

    auto load_kv = [&](int t, int s) {
        const uint32_t sbase = sb + ATT_KV + (uint32_t)s * 32768;
        #pragma unroll
        for (int it = 0; it < 4; it++) {
            int idx = tid + it * 128;
            int r = idx >> 3, c = idx & 7;
            size_t ga = (brow + t * 64 + r) * D_MODEL + hoff + c * 8;
            uint32_t so = sw128((uint32_t)(r * 128 + c * 16));
            cpa16(sbase +         so, g_Kh + ga);
            cpa16(sbase +  8192 + so, g_Kl + ga);
            cpa16(sbase + 16384 + so, g_Vh + ga);
            cpa16(sbase + 24576 + so, g_Vl + ga);
        }
    };

    // Prologue: queue Q + KV(0) in one async group
    #pragma unroll
    for (int it = 0; it < 8; it++) {
        int idx = tid + it * 128;
        int r = idx >> 3, c = idx & 7;      // r 0..127
        size_t ga = (brow + qb * 128 + r) * D_MODEL + hoff + c * 8;
        uint32_t so = sw128((uint32_t)(r * 128 + c * 16));
        cpa16(sb +         so, g_Qh + ga);
        cpa16(sb + 16384 + so, g_Ql + ga);
    }
    load_kv(0, 0);
    CPA_COMMIT();

    uint32_t qh[2][4][4];                   // Q-hi fragments pinned in regs
    float accO[2][8][4];
    float mrow[2][2], lrow[2][2];
    #pragma unroll
    for (int mi = 0; mi < 2; mi++) {
        mrow[mi][0] = mrow[mi][1] = -INFINITY;
        lrow[mi][0] = lrow[mi][1] = 0.f;
        #pragma unroll
        for (int f = 0; f < 8; f++)
            #pragma unroll
            for (int r = 0; r < 4; r++) accO[mi][f][r] = 0.f;
    }

    for (int t = 0; t < SEQ / 64; t++) {
        CPA_WAIT0();
        __syncthreads();
        if (t == 0) {
            #pragma unroll
            for (int kc = 0; kc < 4; kc++)
                #pragma unroll
                for (int mi = 0; mi < 2; mi++) {
                    uint32_t row  = wm + mi * 16 + (lane & 15);
                    uint32_t byte = kc * 32 + (lane >> 4) * 16;
                    ldsm4(qh[mi][kc], sb + sw128(row * 128 + byte));
                }
        }
        if (t + 1 < SEQ / 64) {
            load_kv(t + 1, (t + 1) & 1);
            CPA_COMMIT();
        }
        const uint32_t kvs = sb + ATT_KV + (uint32_t)(t & 1) * 32768;

        // S = Q K^T (log2 domain)
        float accS[2][8][4];
        #pragma unroll
        for (int mi = 0; mi < 2; mi++)
            #pragma unroll
            for (int f = 0; f < 8; f++)
                #pragma unroll
                for (int r = 0; r < 4; r++) accS[mi][f][r] = 0.f;

        #pragma unroll
        for (int kc = 0; kc < 4; kc++) {
            uint32_t ql_[2][4];
            #pragma unroll
            for (int mi = 0; mi < 2; mi++) {
                uint32_t row  = wm + mi * 16 + (lane & 15);
                uint32_t byte = kc * 32 + (lane >> 4) * 16;
                ldsm4(ql_[mi], sb + 16384 + sw128(row * 128 + byte));
            }
            #pragma unroll
            for (int ni = 0; ni < 4; ni++) {
                uint32_t bh[4], bl[4];
                uint32_t tt   = lane >> 3;
                uint32_t row  = ni * 16 + (lane & 7) + 8 * (tt >> 1);
                uint32_t byte = kc * 32 + 16 * (tt & 1);
                uint32_t so   = sw128(row * 128 + byte);
                ldsm4(bh, kvs +        so);
                ldsm4(bl, kvs + 8192 + so);
                #pragma unroll
                for (int sub = 0; sub < 2; sub++)
                    #pragma unroll
                    for (int mi = 0; mi < 2; mi++) {
                        mma_bf16(accS[mi][ni * 2 + sub], qh[mi][kc], bh + sub * 2);
                        mma_bf16(accS[mi][ni * 2 + sub], qh[mi][kc], bl + sub * 2);
                        mma_bf16(accS[mi][ni * 2 + sub], ql_[mi],    bh + sub * 2);
                    }
            }
        }

        // Online softmax per mi (rows g and g+8)
        #pragma unroll
        for (int mi = 0; mi < 2; mi++) {
            float mx0 = -INFINITY, mx1 = -INFINITY;
            #pragma unroll
            for (int f = 0; f < 8; f++) {
                mx0 = fmaxf(mx0, fmaxf(accS[mi][f][0], accS[mi][f][1]));
                mx1 = fmaxf(mx1, fmaxf(accS[mi][f][2], accS[mi][f][3]));
            }
            mx0 = fmaxf(mx0, __shfl_xor_sync(0xffffffffu, mx0, 1));
            mx0 = fmaxf(mx0, __shfl_xor_sync(0xffffffffu, mx0, 2));
            mx1 = fmaxf(mx1, __shfl_xor_sync(0xffffffffu, mx1, 1));
            mx1 = fmaxf(mx1, __shfl_xor_sync(0xffffffffu, mx1, 2));
            float nm0 = fmaxf(mrow[mi][0], mx0);
            float nm1 = fmaxf(mrow[mi][1], mx1);
            float a0 = ex2f(mrow[mi][0] - nm0);
            float a1 = ex2f(mrow[mi][1] - nm1);
            mrow[mi][0] = nm0; mrow[mi][1] = nm1;

            float s0 = 0.f, s1 = 0.f;
            #pragma unroll
            for (int f = 0; f < 8; f++) {
                accS[mi][f][0] = ex2f(accS[mi][f][0] - nm0);
                accS[mi][f][1] = ex2f(accS[mi][f][1] - nm0);
                accS[mi][f][2] = ex2f(accS[mi][f][2] - nm1);
                accS[mi][f][3] = ex2f(accS[mi][f][3] - nm1);
                s0 += accS[mi][f][0] + accS[mi][f][1];
                s1 += accS[mi][f][2] + accS[mi][f][3];
            }
            s0 += __shfl_xor_sync(0xffffffffu, s0, 1);
            s0 += __shfl_xor_sync(0xffffffffu, s0, 2);
            s1 += __shfl_xor_sync(0xffffffffu, s1, 1);
            s1 += __shfl_xor_sync(0xffffffffu, s1, 2);
            lrow[mi][0] = lrow[mi][0] * a0 + s0;
            lrow[mi][1] = lrow[mi][1] * a1 + s1;
            #pragma unroll
            for (int f = 0; f < 8; f++) {
                accO[mi][f][0] *= a0; accO[mi][f][1] *= a0;
                accO[mi][f][2] *= a1; accO[mi][f][3] *= a1;
            }
        }

        // O += P V
        #pragma unroll
        for (int kc = 0; kc < 4; kc++) {
            uint32_t pah[2][4], pal[2][4];
            #pragma unroll
            for (int mi = 0; mi < 2; mi++) {
                const int f0 = 2 * kc, f1 = 2 * kc + 1;
                pah[mi][0] = split_pair(accS[mi][f0][0], accS[mi][f0][1], pal[mi][0]);
                pah[mi][1] = split_pair(accS[mi][f0][2], accS[mi][f0][3], pal[mi][1]);
                pah[mi][2] = split_pair(accS[mi][f1][0], accS[mi][f1][1], pal[mi][2]);
                pah[mi][3] = split_pair(accS[mi][f1][2], accS[mi][f1][3], pal[mi][3]);
            }
            #pragma unroll
            for (int ni = 0; ni < 4; ni++) {
                uint32_t vh[4], vl[4];
                uint32_t row  = kc * 16 + (lane & 7) + 8 * ((lane >> 3) & 1);
                uint32_t byte = ni * 32 + (lane >> 4) * 16;
                uint32_t so   = sw128(row * 128 + byte);
                ldsm4t(vh, kvs + 16384 + so);
                ldsm4t(vl, kvs + 24576 + so);
                #pragma unroll
                for (int sub = 0; sub < 2; sub++)
                    #pragma unroll
                    for (int mi = 0; mi < 2; mi++) {
                        mma_bf16(accO[mi][ni * 2 + sub], pah[mi], vh + sub * 2);
                        mma_bf16(accO[mi][ni * 2 + sub], pah[mi], vl + sub * 2);
                        mma_bf16(accO[mi][ni * 2 + sub], pal[mi], vh + sub * 2);
                    }
            }
        }
    }

    // Normalize + store
    const int g  = lane >> 2;
    const int c2 = (lane & 3) * 2;
    #pragma unroll
    for (int mi = 0; mi < 2; mi++) {
        const float inv0 = 1.f / lrow[mi][0];
        const float inv1 = 1.f / lrow[mi][1];
        const size_t r0 = brow + qb * 128 + wm + mi * 16 + g;
        #pragma unroll
        for (int f = 0; f < 8; f++) {
            const size_t d = hoff + f * 8 + c2;
            float2 v0 = make_float2(accO[mi][f][0] * inv0, accO[mi][f][1] * inv0);
            float2 v1 = make_float2(accO[mi][f][2] * inv1, accO[mi][f][3] * inv1);
            *(float2*)(out +  r0      * D_MODEL + d) = v0;
            *(float2*)(out + (r0 + 8) * D_MODEL + d) = v1;
        }
    }
}

// ---------------------------------------------------------------------------
extern "C" void kernel_launch(void* const* d_in, const int* in_sizes, int n_in,
                              void* d_out, int out_size)
{
    (void)in_sizes; (void)n_in; (void)out_size;
    const float* x  = (const float*)d_in[0];
    const float* Wq = (const float*)d_in[1];
    const float* Wk = (const float*)d_in[2];
    const float* Wv = (const float*)d_in[3];
    float* out = (float*)d_out;

    __nv_bfloat16 *xh, *xl, *wh0, *wl0, *wh1, *wl1, *wh2, *wl2;
    cudaGetSymbolAddress((void**)&xh,  g_xh);
    cudaGetSymbolAddress((void**)&xl,  g_xl);
    cudaGetSymbolAddress((void**)&wh0, g_Wh);
    cudaGetSymbolAddress((void**)&wl0, g_Wl);
    wh1 = wh0 + (size_t)D_MODEL * D_MODEL; wh2 = wh1 + (size_t)D_MODEL * D_MODEL;
    wl1 = wl0 + (size_t)D_MODEL * D_MODEL; wl2 = wl1 + (size_t)D_MODEL * D_MODEL;

    const int nx4 = M_TOTAL * D_MODEL / 4;
    const int nw4 = D_MODEL * D_MODEL / 4;
    split_kernel<<<(nx4 + 255) / 256, 256>>>(x,  xh,  xl,  nx4);
    split_kernel<<<(nw4 + 255) / 256, 256>>>(Wq, wh0, wl0, nw4);
    split_kernel<<<(nw4 + 255) / 256, 256>>>(Wk, wh1, wl1, nw4);
    split_kernel<<<(nw4 + 255) / 256, 256>>>(Wv, wh2, wl2, nw4);

    cudaFuncSetAttribute(qkv_mma, cudaFuncAttributeMaxDynamicSharedMemorySize,
                         2 * QKV_STAGE);
    dim3 ggrid(M_TOTAL / 128, D_MODEL / 128, 3);   // (32, 8, 3)
    qkv_mma<<<ggrid, 256, 2 * QKV_STAGE>>>();

    cudaFuncSetAttribute(attn_mma, cudaFuncAttributeMaxDynamicSharedMemorySize,
                         ATT_SMEM);
    dim3 agrid(SEQ / 128, N_HEADS, BATCH);         // (16, 16, 2)
    attn_mma<<<agrid, 128, ATT_SMEM>>>(out);
}